// round 8
// baseline (speedup 1.0000x reference)
#include <cuda_runtime.h>
#include <mma.h>
#include <cstdint>
#include <math.h>

using namespace nvcuda;

#define Dm 512
#define Tt 2048
#define Bb 4
#define BT 8192
#define FFd 2048
#define Ee 4
#define MAXTOK 8192
#define NCHUNK 16

// smem float strides
#define ALD 36   // A tile row stride (32 + 4), 144B = 9*16 aligned
#define BLD 72   // B tile row stride (64 + 8), 288B = 18*16 aligned
#define CLD 72   // C buffer row stride

#define SM_SPLIT_BYTES 55296   // Ah,Al(2*128*36) + Bh,Bl(2*32*72) floats *4
#define SM_PLAIN_BYTES 36864   // Cbuf 128*72*4 dominates

// ---------------- scratch ----------------
__device__ float g_K[BT * Dm];
__device__ float g_V[BT * Dm];
__device__ float g_wv[BT * Dm];
__device__ float g_tmp[BT * Dm];
__device__ float g_x1[BT * Dm];
__device__ float g_part[Bb * NCHUNK * Dm];
__device__ float g_kvsum[Bb * Dm];
__device__ int   g_counts[Ee];
__device__ int   g_tok[Ee * MAXTOK];
__device__ float g_wslot[Ee * MAXTOK];
__device__ int   g_slottok[BT * 2];
__device__ float g_h[(size_t)Ee * MAXTOK * FFd];
__device__ float g_ybuf[(size_t)Ee * MAXTOK * Dm];

// ---------------- small kernels ----------------
__global__ void zero_counts_kernel() {
    if (threadIdx.x < Ee) g_counts[threadIdx.x] = 0;
}
__global__ void kvsum_partial_kernel() {
    int b = blockIdx.y, tc = blockIdx.x, d = threadIdx.x;
    const float* Kp = g_K + ((long long)b * Tt + (long long)tc * (Tt / NCHUNK)) * Dm;
    const float* Vp = g_V + ((long long)b * Tt + (long long)tc * (Tt / NCHUNK)) * Dm;
    float s = 0.f;
#pragma unroll 8
    for (int t = 0; t < Tt / NCHUNK; ++t)
        s += Kp[(long long)t * Dm + d] * Vp[(long long)t * Dm + d];
    g_part[((long long)b * NCHUNK + tc) * Dm + d] = s;
}
__global__ void kvsum_reduce_kernel() {
    int i = blockIdx.x * 256 + threadIdx.x;
    int b = i >> 9;
    float s = 0.f;
    for (int tc = 0; tc < NCHUNK; ++tc)
        s += g_part[((long long)b * NCHUNK + tc) * Dm + (i & 511)];
    g_kvsum[i] = s;
}

// ---------------- wmma tf32 GEMM ----------------
// C[z][M,N] = A[z][M,K] @ B[z][K,N] + bias[z][N]
// SPLIT: 2-term error-free tf32 decomposition (fp32-grade accuracy).
// MODE 0 plain; MODE 1 gather A rows via g_tok + relu + row mask; MODE 2 row scale by g_wslot + mask.
template<int MODE, bool SPLIT>
__global__ __launch_bounds__(256)
void gemm_wmma(const float* __restrict__ A, const float* __restrict__ B,
               const float* __restrict__ bias, float* __restrict__ C,
               int M, int N, int K,
               long long sA, long long sB, long long sBias, long long sC)
{
    extern __shared__ float sm[];
    const int z = blockIdx.z;
    const int cnt = (MODE == 0) ? M : g_counts[z];
    const int row0 = blockIdx.y * 128;
    if (row0 >= cnt) return;
    const int col0 = blockIdx.x * 64;
    A += (long long)z * sA;
    B += (long long)z * sB;
    C += (long long)z * sC;
    const float* bz = bias + (long long)z * sBias;

    const int tid = threadIdx.x;
    const int warpId = tid >> 5;
    const int warpM = warpId & 3;       // 4 row-warps of 32
    const int warpN = warpId >> 2;      // 2 col-warps of 32

    float* Ah = sm;                                       // 128 x ALD
    float* Al = SPLIT ? (sm + 128 * ALD) : sm;            // 128 x ALD
    float* Bh = sm + (SPLIT ? 2 : 1) * 128 * ALD;         // 32 x BLD
    float* Bl = SPLIT ? (Bh + 32 * BLD) : Bh;             // 32 x BLD
    float* Cbuf = sm;                                     // 128 x CLD (reuse)

    __shared__ int toks[128];
    if (MODE == 1 && tid < 128) {
        int slot = row0 + tid;
        toks[tid] = (slot < cnt) ? g_tok[z * MAXTOK + slot] : 0;
    }
    if (MODE == 1) __syncthreads();

    wmma::fragment<wmma::accumulator, 16, 16, 8, float> acc[2][2];
#pragma unroll
    for (int i = 0; i < 2; i++)
#pragma unroll
        for (int j = 0; j < 2; j++) wmma::fill_fragment(acc[i][j], 0.f);

    for (int k0 = 0; k0 < K; k0 += 32) {
        // load A tile 128x32 (4 float4 / thread)
#pragma unroll
        for (int p = 0; p < 4; p++) {
            int f = tid + p * 256;
            int r = f >> 3, c4 = f & 7;
            int rowIdx = (MODE == 1) ? toks[r] : (row0 + r);
            float4 v = *reinterpret_cast<const float4*>(A + (long long)rowIdx * K + k0 + c4 * 4);
            float* dsth = Ah + r * ALD + c4 * 4;
            if (SPLIT) {
                float4 h, l;
                h.x = __uint_as_float(__float_as_uint(v.x) & 0xFFFFE000u); l.x = v.x - h.x;
                h.y = __uint_as_float(__float_as_uint(v.y) & 0xFFFFE000u); l.y = v.y - h.y;
                h.z = __uint_as_float(__float_as_uint(v.z) & 0xFFFFE000u); l.z = v.z - h.z;
                h.w = __uint_as_float(__float_as_uint(v.w) & 0xFFFFE000u); l.w = v.w - h.w;
                *reinterpret_cast<float4*>(dsth) = h;
                *reinterpret_cast<float4*>(Al + r * ALD + c4 * 4) = l;
            } else {
                *reinterpret_cast<float4*>(dsth) = v;
            }
        }
        // load B tile 32x64 (2 float4 / thread)
#pragma unroll
        for (int p = 0; p < 2; p++) {
            int f = tid + p * 256;
            int r = f >> 4, c4 = f & 15;
            float4 v = *reinterpret_cast<const float4*>(B + (long long)(k0 + r) * N + col0 + c4 * 4);
            float* dsth = Bh + r * BLD + c4 * 4;
            if (SPLIT) {
                float4 h, l;
                h.x = __uint_as_float(__float_as_uint(v.x) & 0xFFFFE000u); l.x = v.x - h.x;
                h.y = __uint_as_float(__float_as_uint(v.y) & 0xFFFFE000u); l.y = v.y - h.y;
                h.z = __uint_as_float(__float_as_uint(v.z) & 0xFFFFE000u); l.z = v.z - h.z;
                h.w = __uint_as_float(__float_as_uint(v.w) & 0xFFFFE000u); l.w = v.w - h.w;
                *reinterpret_cast<float4*>(dsth) = h;
                *reinterpret_cast<float4*>(Bl + r * BLD + c4 * 4) = l;
            } else {
                *reinterpret_cast<float4*>(dsth) = v;
            }
        }
        __syncthreads();

#pragma unroll
        for (int ks = 0; ks < 4; ks++) {
            wmma::fragment<wmma::matrix_a, 16, 16, 8, wmma::precision::tf32, wmma::row_major> ah[2], al[2];
            wmma::fragment<wmma::matrix_b, 16, 16, 8, wmma::precision::tf32, wmma::row_major> bh[2], bl[2];
#pragma unroll
            for (int i = 0; i < 2; i++) {
                wmma::load_matrix_sync(ah[i], Ah + (warpM * 32 + i * 16) * ALD + ks * 8, ALD);
                if (SPLIT)
                    wmma::load_matrix_sync(al[i], Al + (warpM * 32 + i * 16) * ALD + ks * 8, ALD);
            }
#pragma unroll
            for (int j = 0; j < 2; j++) {
                wmma::load_matrix_sync(bh[j], Bh + (ks * 8) * BLD + warpN * 32 + j * 16, BLD);
                if (SPLIT)
                    wmma::load_matrix_sync(bl[j], Bl + (ks * 8) * BLD + warpN * 32 + j * 16, BLD);
            }
#pragma unroll
            for (int i = 0; i < 2; i++)
#pragma unroll
                for (int j = 0; j < 2; j++) {
                    wmma::mma_sync(acc[i][j], ah[i], bh[j], acc[i][j]);
                    if (SPLIT) {
                        wmma::mma_sync(acc[i][j], ah[i], bl[j], acc[i][j]);
                        wmma::mma_sync(acc[i][j], al[i], bh[j], acc[i][j]);
                    }
                }
        }
        __syncthreads();
    }

    // write accumulators to smem C buffer
#pragma unroll
    for (int i = 0; i < 2; i++)
#pragma unroll
        for (int j = 0; j < 2; j++)
            wmma::store_matrix_sync(Cbuf + (warpM * 32 + i * 16) * CLD + warpN * 32 + j * 16,
                                    acc[i][j], CLD, wmma::mem_row_major);
    __syncthreads();

    // epilogue: 8 float4 / thread
#pragma unroll
    for (int it = 0; it < 8; it++) {
        int f = tid + it * 256;
        int r = f >> 4, c4 = f & 15;
        int grow = row0 + r;
        if (MODE != 0 && grow >= cnt) continue;
        float4 v = *reinterpret_cast<const float4*>(Cbuf + r * CLD + c4 * 4);
        int col = col0 + c4 * 4;
        v.x += __ldg(bz + col + 0);
        v.y += __ldg(bz + col + 1);
        v.z += __ldg(bz + col + 2);
        v.w += __ldg(bz + col + 3);
        if (MODE == 1) {
            v.x = fmaxf(v.x, 0.f); v.y = fmaxf(v.y, 0.f);
            v.z = fmaxf(v.z, 0.f); v.w = fmaxf(v.w, 0.f);
        }
        if (MODE == 2) {
            float w = g_wslot[z * MAXTOK + grow];
            v.x *= w; v.y *= w; v.z *= w; v.w *= w;
        }
        *reinterpret_cast<float4*>(C + (long long)grow * N + col) = v;
    }
}

// ---------------- LN1 ----------------
__global__ __launch_bounds__(256) void add_ln1_kernel(
    const float* __restrict__ x, const float* __restrict__ g, const float* __restrict__ b)
{
    int t = blockIdx.x, tid = threadIdx.x;
    const float* xr = x + (long long)t * Dm;
    const float* tr = g_tmp + (long long)t * Dm;
    float v0 = xr[tid] + tr[tid];
    float v1 = xr[tid + 256] + tr[tid + 256];
    __shared__ float red[256];
    red[tid] = v0 + v1;
    __syncthreads();
    for (int off = 128; off; off >>= 1) { if (tid < off) red[tid] += red[tid + off]; __syncthreads(); }
    float mu = red[0] * (1.0f / 512.0f);
    __syncthreads();
    float d0 = v0 - mu, d1 = v1 - mu;
    red[tid] = d0 * d0 + d1 * d1;
    __syncthreads();
    for (int off = 128; off; off >>= 1) { if (tid < off) red[tid] += red[tid + off]; __syncthreads(); }
    float inv = rsqrtf(red[0] * (1.0f / 512.0f) + 1e-5f);
    g_x1[(long long)t * Dm + tid]       = d0 * inv * g[tid] + b[tid];
    g_x1[(long long)t * Dm + tid + 256] = d1 * inv * g[tid + 256] + b[tid + 256];
}

// ---------------- gate (exact fp32) ----------------
__global__ __launch_bounds__(128) void gate_kernel(
    const float* __restrict__ Wg, const float* __restrict__ bg)
{
    int t = blockIdx.x, tid = threadIdx.x;
    const float* xr = g_x1 + (long long)t * Dm;
    float p0 = 0, p1 = 0, p2 = 0, p3 = 0;
    const float4* Wg4 = reinterpret_cast<const float4*>(Wg);
    for (int d = tid; d < Dm; d += 128) {
        float xv = xr[d];
        float4 w = Wg4[d];
        p0 = fmaf(xv, w.x, p0); p1 = fmaf(xv, w.y, p1);
        p2 = fmaf(xv, w.z, p2); p3 = fmaf(xv, w.w, p3);
    }
    __shared__ float smr[4][128];
    smr[0][tid] = p0; smr[1][tid] = p1; smr[2][tid] = p2; smr[3][tid] = p3;
    __syncthreads();
    for (int off = 64; off; off >>= 1) {
        if (tid < off) {
            smr[0][tid] += smr[0][tid + off];
            smr[1][tid] += smr[1][tid + off];
            smr[2][tid] += smr[2][tid + off];
            smr[3][tid] += smr[3][tid + off];
        }
        __syncthreads();
    }
    if (tid == 0) {
        float s[4] = { smr[0][0] + bg[0], smr[1][0] + bg[1], smr[2][0] + bg[2], smr[3][0] + bg[3] };
        float m = fmaxf(fmaxf(s[0], s[1]), fmaxf(s[2], s[3]));
        float ex[4]; float sum = 0.f;
        for (int e = 0; e < 4; e++) { ex[e] = expf(s[e] - m); sum += ex[e]; }
        float invs = 1.0f / sum;
        float pr[4];
        for (int e = 0; e < 4; e++) pr[e] = ex[e] * invs;
        int i0 = 0;
        for (int e = 1; e < 4; e++) if (pr[e] > pr[i0]) i0 = e;
        int i1 = -1;
        for (int e = 0; e < 4; e++) {
            if (e == i0) continue;
            if (i1 < 0 || pr[e] > pr[i1]) i1 = e;
        }
        int s0 = atomicAdd(&g_counts[i0], 1);
        g_tok[i0 * MAXTOK + s0] = t;
        g_wslot[i0 * MAXTOK + s0] = pr[i0];
        g_slottok[2 * t] = i0 * MAXTOK + s0;
        int s1 = atomicAdd(&g_counts[i1], 1);
        g_tok[i1 * MAXTOK + s1] = t;
        g_wslot[i1 * MAXTOK + s1] = pr[i1];
        g_slottok[2 * t + 1] = i1 * MAXTOK + s1;
    }
}

// ---------------- combine + LN2 ----------------
__global__ __launch_bounds__(256) void combine_ln2_kernel(
    const float* __restrict__ g, const float* __restrict__ b, float* __restrict__ out)
{
    int t = blockIdx.x, tid = threadIdx.x;
    int s0 = g_slottok[2 * t], s1 = g_slottok[2 * t + 1];
    const float* xr = g_x1 + (long long)t * Dm;
    const float* y0 = g_ybuf + (long long)s0 * Dm;
    const float* y1 = g_ybuf + (long long)s1 * Dm;
    float v0 = xr[tid] + y0[tid] + y1[tid];
    float v1 = xr[tid + 256] + y0[tid + 256] + y1[tid + 256];
    __shared__ float red[256];
    red[tid] = v0 + v1;
    __syncthreads();
    for (int off = 128; off; off >>= 1) { if (tid < off) red[tid] += red[tid + off]; __syncthreads(); }
    float mu = red[0] * (1.0f / 512.0f);
    __syncthreads();
    float d0 = v0 - mu, d1 = v1 - mu;
    red[tid] = d0 * d0 + d1 * d1;
    __syncthreads();
    for (int off = 128; off; off >>= 1) { if (tid < off) red[tid] += red[tid + off]; __syncthreads(); }
    float inv = rsqrtf(red[0] * (1.0f / 512.0f) + 1e-5f);
    out[(long long)t * Dm + tid]       = d0 * inv * g[tid] + b[tid];
    out[(long long)t * Dm + tid + 256] = d1 * inv * g[tid + 256] + b[tid + 256];
}

// ---------------- launch ----------------
extern "C" void kernel_launch(void* const* d_in, const int* in_sizes, int n_in,
                              void* d_out, int out_size)
{
    const float* x    = (const float*)d_in[0];
    const float* fb   = (const float*)d_in[1];
    const float* Wk   = (const float*)d_in[2];
    const float* bk   = (const float*)d_in[3];
    const float* Wv   = (const float*)d_in[4];
    const float* bv   = (const float*)d_in[5];
    const float* Wo   = (const float*)d_in[6];
    const float* bo   = (const float*)d_in[7];
    const float* ln1g = (const float*)d_in[8];
    const float* ln1b = (const float*)d_in[9];
    const float* Wg   = (const float*)d_in[10];
    const float* bg   = (const float*)d_in[11];
    const float* W1   = (const float*)d_in[12];
    const float* b1   = (const float*)d_in[13];
    const float* W2   = (const float*)d_in[14];
    const float* b2   = (const float*)d_in[15];
    const float* ln2g = (const float*)d_in[16];
    const float* ln2b = (const float*)d_in[17];
    float* out = (float*)d_out;

    float *pK, *pV, *pwv, *ptmp, *pkvs, *ph, *pyb, *px1;
    cudaGetSymbolAddress((void**)&pK,   g_K);
    cudaGetSymbolAddress((void**)&pV,   g_V);
    cudaGetSymbolAddress((void**)&pwv,  g_wv);
    cudaGetSymbolAddress((void**)&ptmp, g_tmp);
    cudaGetSymbolAddress((void**)&pkvs, g_kvsum);
    cudaGetSymbolAddress((void**)&ph,   g_h);
    cudaGetSymbolAddress((void**)&pyb,  g_ybuf);
    cudaGetSymbolAddress((void**)&px1,  g_x1);

    cudaFuncSetAttribute(gemm_wmma<0, true>,  cudaFuncAttributeMaxDynamicSharedMemorySize, SM_SPLIT_BYTES);
    cudaFuncSetAttribute(gemm_wmma<1, false>, cudaFuncAttributeMaxDynamicSharedMemorySize, SM_PLAIN_BYTES);
    cudaFuncSetAttribute(gemm_wmma<2, false>, cudaFuncAttributeMaxDynamicSharedMemorySize, SM_PLAIN_BYTES);

    zero_counts_kernel<<<1, 32>>>();

    // K = x@Wk + bk ; V = x@Wv + bv    (split tf32, fp32-grade)
    gemm_wmma<0, true><<<dim3(8, 64, 1), 256, SM_SPLIT_BYTES>>>(
        x, Wk, bk, pK, BT, Dm, Dm, 0, 0, 0, 0);
    gemm_wmma<0, true><<<dim3(8, 64, 1), 256, SM_SPLIT_BYTES>>>(
        x, Wv, bv, pV, BT, Dm, Dm, 0, 0, 0, 0);

    // kv_sum (deterministic two-stage fp32)
    kvsum_partial_kernel<<<dim3(NCHUNK, Bb), 512>>>();
    kvsum_reduce_kernel<<<8, 256>>>();

    // wv[b] = fb[b] @ V[b] + kvsum[b]
    gemm_wmma<0, true><<<dim3(8, 16, Bb), 256, SM_SPLIT_BYTES>>>(
        fb, pV, pkvs, pwv, Tt, Dm, Tt,
        (long long)Tt * Tt, (long long)Tt * Dm, Dm, (long long)Tt * Dm);

    // tmp = wv @ Wo + bo
    gemm_wmma<0, true><<<dim3(8, 64, 1), 256, SM_SPLIT_BYTES>>>(
        pwv, Wo, bo, ptmp, BT, Dm, Dm, 0, 0, 0, 0);

    add_ln1_kernel<<<BT, 256>>>(x, ln1g, ln1b);
    gate_kernel<<<BT, 128>>>(Wg, bg);

    // MoE GEMM1: h = relu(x1[tok] @ W1[e] + b1[e])   (single tf32)
    gemm_wmma<1, false><<<dim3(32, 64, Ee), 256, SM_PLAIN_BYTES>>>(
        px1, W1, b1, ph, MAXTOK, FFd, Dm,
        0, (long long)Dm * FFd, FFd, (long long)MAXTOK * FFd);

    // MoE GEMM2: ybuf = w * (h @ W2[e] + b2[e])      (single tf32)
    gemm_wmma<2, false><<<dim3(8, 64, Ee), 256, SM_PLAIN_BYTES>>>(
        ph, W2, b2, pyb, MAXTOK, Dm, FFd,
        (long long)MAXTOK * FFd, (long long)FFd * Dm, Dm, (long long)MAXTOK * Dm);

    combine_ln2_kernel<<<BT, 256>>>(ln2g, ln2b, out);
}